// round 9
// baseline (speedup 1.0000x reference)
#include <cuda_runtime.h>
#include <cuda_bf16.h>
#include <cstdint>

#define E_ 8
#define H_ 1024
#define I_ 2048
#define T_ 1024

#define RSTB  80                      // smem row stride bytes (64B data + 16B pad)
#define TILEB (128 * RSTB)            // 10240 B per 128-row tile
#define STGB  (3 * TILEB)             // A_hi + A_lo + B = 30720 B
#define NSTG  4
#define SMEMSZ (NSTG * STGB)          // 122880 B

// ---------------- scratch ----------------
__device__ int   g_cnt[E_];
__device__ int   g_tok[E_ * T_];
__device__ int   g_slot[E_ * T_];
__device__ float g_gate[E_ * T_];
__device__ __nv_bfloat16 g_xh[T_ * H_];
__device__ __nv_bfloat16 g_xl[T_ * H_];
__device__ __nv_bfloat16 g_w13b[(size_t)E_ * 2 * I_ * H_];
__device__ __nv_bfloat16 g_w2b[(size_t)E_ * H_ * I_];
__device__ __nv_bfloat16 g_acth[(size_t)E_ * T_ * I_];
__device__ __nv_bfloat16 g_actl[(size_t)E_ * T_ * I_];
__device__ float g_ypart[(size_t)T_ * 2 * H_];

// ---------------- helpers ----------------
__device__ __forceinline__ void cp16(uint32_t sa, const void* g) {
    asm volatile("cp.async.cg.shared.global [%0], [%1], 16;\n" :: "r"(sa), "l"(g));
}
__device__ __forceinline__ void cp_commit() { asm volatile("cp.async.commit_group;\n"); }
__device__ __forceinline__ void cp_wait2()  { asm volatile("cp.async.wait_group 2;\n"); }
__device__ __forceinline__ void cp_wait0()  { asm volatile("cp.async.wait_group 0;\n"); }

__device__ __forceinline__ uint32_t pack_bf2(float lo, float hi) {
    uint32_t r;
    asm("cvt.rn.bf16x2.f32 %0, %1, %2;" : "=r"(r) : "f"(hi), "f"(lo));
    return r;
}
__device__ __forceinline__ float bf_rt(float v) {
    return __bfloat162float(__float2bfloat16_rn(v));
}
__device__ __forceinline__ void ldsm4(uint32_t r[4], uint32_t a) {
    asm volatile("ldmatrix.sync.aligned.m8n8.x4.shared.b16 {%0,%1,%2,%3}, [%4];"
        : "=r"(r[0]), "=r"(r[1]), "=r"(r[2]), "=r"(r[3]) : "r"(a));
}
__device__ __forceinline__ void hmma(float c[4], const uint32_t a[4], uint32_t b0, uint32_t b1) {
    asm volatile(
        "mma.sync.aligned.m16n8k16.row.col.f32.bf16.bf16.f32 "
        "{%0,%1,%2,%3}, {%4,%5,%6,%7}, {%8,%9}, {%0,%1,%2,%3};\n"
        : "+f"(c[0]), "+f"(c[1]), "+f"(c[2]), "+f"(c[3])
        : "r"(a[0]), "r"(a[1]), "r"(a[2]), "r"(a[3]), "r"(b0), "r"(b1));
}

// ---------------- small kernels ----------------
__global__ void zero_cnt_kernel() { if (threadIdx.x < E_) g_cnt[threadIdx.x] = 0; }

__global__ void presplit_kernel(const float* __restrict__ x) {
    int i = blockIdx.x * blockDim.x + threadIdx.x;
    float4 v = reinterpret_cast<const float4*>(x)[i];
    float h0 = bf_rt(v.x), h1 = bf_rt(v.y), h2 = bf_rt(v.z), h3 = bf_rt(v.w);
    reinterpret_cast<uint2*>(g_xh)[i] = make_uint2(pack_bf2(v.x, v.y), pack_bf2(v.z, v.w));
    reinterpret_cast<uint2*>(g_xl)[i] =
        make_uint2(pack_bf2(v.x - h0, v.y - h1), pack_bf2(v.z - h2, v.w - h3));
}

__global__ void convw_kernel(const float* __restrict__ w13, const float* __restrict__ w2) {
    size_t i = (size_t)blockIdx.x * blockDim.x + threadIdx.x;
    const size_t N13 = (size_t)E_ * 2 * I_ * H_;
    size_t base = i * 8;
    const float4* src;
    uint2* dst;
    if (base < N13) {
        src = reinterpret_cast<const float4*>(w13 + base);
        dst = reinterpret_cast<uint2*>(g_w13b + base);
    } else {
        base -= N13;
        src = reinterpret_cast<const float4*>(w2 + base);
        dst = reinterpret_cast<uint2*>(g_w2b + base);
    }
    float4 a = __ldg(src), b = __ldg(src + 1);
    dst[0] = make_uint2(pack_bf2(a.x, a.y), pack_bf2(a.z, a.w));
    dst[1] = make_uint2(pack_bf2(b.x, b.y), pack_bf2(b.z, b.w));
}

__global__ void router_kernel(const float* __restrict__ logits) {
    int t = blockIdx.x * blockDim.x + threadIdx.x;
    if (t >= T_) return;
    float l[E_]; float mx = -1e30f;
#pragma unroll
    for (int e = 0; e < E_; e++) { l[e] = logits[t * E_ + e]; mx = fmaxf(mx, l[e]); }
    float p[E_];
#pragma unroll
    for (int e = 0; e < E_; e++) p[e] = __expf(l[e] - mx);
    int i1 = 0, i2 = -1; float v1 = p[0], v2 = -1.0f;
#pragma unroll
    for (int e = 1; e < E_; e++) {
        float pe = p[e];
        if (pe > v1) { v2 = v1; i2 = i1; v1 = pe; i1 = e; }
        else if (pe > v2) { v2 = pe; i2 = e; }
    }
    float inv = 1.0f / (v1 + v2);
    int pos1 = atomicAdd(&g_cnt[i1], 1);
    g_tok[i1 * T_ + pos1] = t; g_slot[i1 * T_ + pos1] = 0; g_gate[i1 * T_ + pos1] = v1 * inv;
    int pos2 = atomicAdd(&g_cnt[i2], 1);
    g_tok[i2 * T_ + pos2] = t; g_slot[i2 * T_ + pos2] = 1; g_gate[i2 * T_ + pos2] = v2 * inv;
}

// =============== GEMM1: 128m x 64n (dual G|L), bf16 hi/lo, fused GLU ===============
__global__ void __launch_bounds__(256, 1) gemm1_kernel(const float* __restrict__ b13)
{
    int e = blockIdx.z;
    int cnt = g_cnt[e];
    int m0 = blockIdx.y * 128;
    if (m0 >= cnt) return;
    int n0 = blockIdx.x * 64;
    int tid = threadIdx.x;

    extern __shared__ char smem[];
    uint32_t sb = (uint32_t)__cvta_generic_to_shared(smem);

    // ---- fill setup ----
    int lr = tid >> 1, lh = tid & 1;
    int mg = m0 + lr; if (mg >= cnt) mg = cnt - 1;
    size_t axoff = (size_t)g_tok[e * T_ + mg] * H_ + lh * 16;
    const __nv_bfloat16* ah = g_xh + axoff;
    const __nv_bfloat16* al = g_xl + axoff;
    size_t brow = (lr < 64) ? ((size_t)e * 2 * I_ + n0 + lr)
                            : ((size_t)e * 2 * I_ + I_ + n0 + (lr - 64));
    const __nv_bfloat16* bb = g_w13b + brow * H_ + lh * 16;
    uint32_t adst = sb + lr * RSTB + lh * 32;
    uint32_t bdst = sb + 2 * TILEB + lr * RSTB + lh * 32;

#define FILL1(c, s) {                                                    \
        uint32_t o_ = (s) * STGB;                                        \
        const __nv_bfloat16* ph_ = ah + (c) * 32;                        \
        const __nv_bfloat16* pl_ = al + (c) * 32;                        \
        const __nv_bfloat16* pb_ = bb + (c) * 32;                        \
        cp16(adst + o_, ph_); cp16(adst + o_ + 16, ph_ + 8);             \
        cp16(adst + o_ + TILEB, pl_); cp16(adst + o_ + TILEB + 16, pl_ + 8); \
        cp16(bdst + o_, pb_); cp16(bdst + o_ + 16, pb_ + 8);             \
        cp_commit(); }

    // ---- compute setup ----
    int lane = tid & 31, warp = tid >> 5;
    int wm = warp & 3, wn = warp >> 2;      // warp 32m x (32G + 32L)
    int gid = lane >> 2, tig = lane & 3;

    uint32_t aAH = sb + (wm * 32 + (lane & 15)) * RSTB + (lane >> 4) * 16;
    uint32_t aAL = aAH + TILEB;
    int brl = ((lane >> 4) & 1) * 8 + (lane & 7);
    int bko = ((lane >> 3) & 1) * 16;
    uint32_t bA = sb + 2 * TILEB + bko;
    uint32_t tb[4];
    tb[0] = bA + (wn * 32 + brl) * RSTB;
    tb[1] = bA + (wn * 32 + 16 + brl) * RSTB;
    tb[2] = bA + (64 + wn * 32 + brl) * RSTB;
    tb[3] = bA + (64 + wn * 32 + 16 + brl) * RSTB;

    // double-buffered fragments
    uint32_t bfr[2][4][4], afh[2][2][4], afl[2][2][4];
    float acc[2][8][4];
#pragma unroll
    for (int i = 0; i < 2; i++)
#pragma unroll
        for (int j = 0; j < 8; j++)
#pragma unroll
            for (int k = 0; k < 4; k++) acc[i][j][k] = 0.f;

#define LDF1(p, ko) {                                                    \
        _Pragma("unroll")                                                \
        for (int g = 0; g < 4; g++) ldsm4(bfr[p][g], tb[g] + (ko));      \
        ldsm4(afh[p][0], aAH + (ko)); ldsm4(afh[p][1], aAH + (ko) + 16 * RSTB); \
        ldsm4(afl[p][0], aAL + (ko)); ldsm4(afl[p][1], aAL + (ko) + 16 * RSTB); }

#define MMA1(p) {                                                        \
        _Pragma("unroll")                                                \
        for (int g = 0; g < 4; g++)                                      \
            _Pragma("unroll")                                            \
            for (int mi = 0; mi < 2; mi++) {                             \
                hmma(acc[mi][2 * g],     afh[p][mi], bfr[p][g][0], bfr[p][g][1]); \
                hmma(acc[mi][2 * g + 1], afh[p][mi], bfr[p][g][2], bfr[p][g][3]); \
            }                                                            \
        _Pragma("unroll")                                                \
        for (int g = 0; g < 4; g++)                                      \
            _Pragma("unroll")                                            \
            for (int mi = 0; mi < 2; mi++) {                             \
                hmma(acc[mi][2 * g],     afl[p][mi], bfr[p][g][0], bfr[p][g][1]); \
                hmma(acc[mi][2 * g + 1], afl[p][mi], bfr[p][g][2], bfr[p][g][3]); \
            } }

    // ---- prologue: 3 chunks in flight ----
    FILL1(0, 0); FILL1(1, 1); FILL1(2, 2);

    const int NK = H_ / 32;   // 32
#pragma unroll 1
    for (int kt = 0; kt < NK; ++kt) {
        int st = kt % NSTG;
        cp_wait2();
        __syncthreads();
        int cf = kt + 3;
        if (cf < NK) { FILL1(cf, cf % NSTG); } else { cp_commit(); }
        uint32_t so = st * STGB;
        LDF1(0, so);
        LDF1(1, so + 32);     // issue next-phase loads before computing phase 0
        MMA1(0);
        MMA1(1);
    }

    // ---- epilogue ----
    float bgv[4][2], blv[4][2];
#pragma unroll
    for (int ni = 0; ni < 4; ni++) {
        int n = n0 + wn * 32 + ni * 8 + tig * 2;
        bgv[ni][0] = __ldg(&b13[(size_t)e * 2 * I_ + n]);
        bgv[ni][1] = __ldg(&b13[(size_t)e * 2 * I_ + n + 1]);
        blv[ni][0] = __ldg(&b13[(size_t)e * 2 * I_ + I_ + n]);
        blv[ni][1] = __ldg(&b13[(size_t)e * 2 * I_ + I_ + n + 1]);
    }
    size_t actbase = (size_t)e * T_ * I_;
#pragma unroll
    for (int mi = 0; mi < 2; mi++) {
#pragma unroll
        for (int rr = 0; rr < 2; rr++) {
            int m = m0 + wm * 32 + mi * 16 + gid + rr * 8;
            if (m >= cnt) continue;
            size_t rowoff = actbase + (size_t)m * I_;
#pragma unroll
            for (int ni = 0; ni < 4; ni++) {
                int n = n0 + wn * 32 + ni * 8 + tig * 2;
                float g0 = acc[mi][ni][rr * 2 + 0] + bgv[ni][0];
                float g1 = acc[mi][ni][rr * 2 + 1] + bgv[ni][1];
                float l0 = acc[mi][4 + ni][rr * 2 + 0] + blv[ni][0];
                float l1 = acc[mi][4 + ni][rr * 2 + 1] + blv[ni][1];
                float a0 = g0 * (1.f / (1.f + __expf(-1.702f * g0))) * (l0 + 1.0f);
                float a1 = g1 * (1.f / (1.f + __expf(-1.702f * g1))) * (l1 + 1.0f);
                float h0 = bf_rt(a0), h1 = bf_rt(a1);
                *reinterpret_cast<uint32_t*>(g_acth + rowoff + n) = pack_bf2(a0, a1);
                *reinterpret_cast<uint32_t*>(g_actl + rowoff + n) = pack_bf2(a0 - h0, a1 - h1);
            }
        }
    }
#undef FILL1
#undef LDF1
#undef MMA1
}

// =============== GEMM2: 128m x 128n, bf16 hi/lo, fused bias+gate+scatter ===============
__global__ void __launch_bounds__(256, 1) gemm2_kernel(const float* __restrict__ b2)
{
    int e = blockIdx.z;
    int cnt = g_cnt[e];
    int m0 = blockIdx.y * 128;
    if (m0 >= cnt) return;
    int n0 = blockIdx.x * 128;
    int tid = threadIdx.x;

    extern __shared__ char smem[];
    uint32_t sb = (uint32_t)__cvta_generic_to_shared(smem);

    int lr = tid >> 1, lh = tid & 1;
    size_t aoff = (size_t)(e * T_ + m0 + lr) * I_ + lh * 16;
    const __nv_bfloat16* ah = g_acth + aoff;
    const __nv_bfloat16* al = g_actl + aoff;
    const __nv_bfloat16* bb = g_w2b + (size_t)(e * H_ + n0 + lr) * I_ + lh * 16;
    uint32_t adst = sb + lr * RSTB + lh * 32;
    uint32_t bdst = sb + 2 * TILEB + lr * RSTB + lh * 32;

#define FILL2(c, s) {                                                    \
        uint32_t o_ = (s) * STGB;                                        \
        const __nv_bfloat16* ph_ = ah + (c) * 32;                        \
        const __nv_bfloat16* pl_ = al + (c) * 32;                        \
        const __nv_bfloat16* pb_ = bb + (c) * 32;                        \
        cp16(adst + o_, ph_); cp16(adst + o_ + 16, ph_ + 8);             \
        cp16(adst + o_ + TILEB, pl_); cp16(adst + o_ + TILEB + 16, pl_ + 8); \
        cp16(bdst + o_, pb_); cp16(bdst + o_ + 16, pb_ + 8);             \
        cp_commit(); }

    int lane = tid & 31, warp = tid >> 5;
    int wm = warp & 3, wn = warp >> 2;      // warp 32m x 64n
    int gid = lane >> 2, tig = lane & 3;

    uint32_t aAH = sb + (wm * 32 + (lane & 15)) * RSTB + (lane >> 4) * 16;
    uint32_t aAL = aAH + TILEB;
    int brl = ((lane >> 4) & 1) * 8 + (lane & 7);
    int bko = ((lane >> 3) & 1) * 16;
    uint32_t bA = sb + 2 * TILEB + bko;
    uint32_t tb[4];
#pragma unroll
    for (int g = 0; g < 4; g++) tb[g] = bA + (wn * 64 + g * 16 + brl) * RSTB;

    uint32_t bfr[2][4][4], afh[2][2][4], afl[2][2][4];
    float acc[2][8][4];
#pragma unroll
    for (int i = 0; i < 2; i++)
#pragma unroll
        for (int j = 0; j < 8; j++)
#pragma unroll
            for (int k = 0; k < 4; k++) acc[i][j][k] = 0.f;

#define LDF2(p, ko) {                                                    \
        _Pragma("unroll")                                                \
        for (int g = 0; g < 4; g++) ldsm4(bfr[p][g], tb[g] + (ko));      \
        ldsm4(afh[p][0], aAH + (ko)); ldsm4(afh[p][1], aAH + (ko) + 16 * RSTB); \
        ldsm4(afl[p][0], aAL + (ko)); ldsm4(afl[p][1], aAL + (ko) + 16 * RSTB); }

#define MMA2(p) {                                                        \
        _Pragma("unroll")                                                \
        for (int g = 0; g < 4; g++)                                      \
            _Pragma("unroll")                                            \
            for (int mi = 0; mi < 2; mi++) {                             \
                hmma(acc[mi][2 * g],     afh[p][mi], bfr[p][g][0], bfr[p][g][1]); \
                hmma(acc[mi][2 * g + 1], afh[p][mi], bfr[p][g][2], bfr[p][g][3]); \
            }                                                            \
        _Pragma("unroll")                                                \
        for (int g = 0; g < 4; g++)                                      \
            _Pragma("unroll")                                            \
            for (int mi = 0; mi < 2; mi++) {                             \
                hmma(acc[mi][2 * g],     afl[p][mi], bfr[p][g][0], bfr[p][g][1]); \
                hmma(acc[mi][2 * g + 1], afl[p][mi], bfr[p][g][2], bfr[p][g][3]); \
            } }

    FILL2(0, 0); FILL2(1, 1); FILL2(2, 2);

    const int NK = I_ / 32;   // 64
#pragma unroll 1
    for (int kt = 0; kt < NK; ++kt) {
        int st = kt % NSTG;
        cp_wait2();
        __syncthreads();
        int cf = kt + 3;
        if (cf < NK) { FILL2(cf, cf % NSTG); } else { cp_commit(); }
        uint32_t so = st * STGB;
        LDF2(0, so);
        LDF2(1, so + 32);
        MMA2(0);
        MMA2(1);
    }

    float bv[8][2];
#pragma unroll
    for (int ni = 0; ni < 8; ni++) {
        int n = n0 + wn * 64 + ni * 8 + tig * 2;
        bv[ni][0] = __ldg(&b2[(size_t)e * H_ + n]);
        bv[ni][1] = __ldg(&b2[(size_t)e * H_ + n + 1]);
    }
#pragma unroll
    for (int mi = 0; mi < 2; mi++) {
#pragma unroll
        for (int rr = 0; rr < 2; rr++) {
            int m = m0 + wm * 32 + mi * 16 + gid + rr * 8;
            if (m >= cnt) continue;
            int tok = g_tok[e * T_ + m];
            int slot = g_slot[e * T_ + m];
            float gt = g_gate[e * T_ + m];
            float* dst = g_ypart + (size_t)(tok * 2 + slot) * H_;
#pragma unroll
            for (int ni = 0; ni < 8; ni++) {
                int n = n0 + wn * 64 + ni * 8 + tig * 2;
                float v0 = (acc[mi][ni][rr * 2 + 0] + bv[ni][0]) * gt;
                float v1 = (acc[mi][ni][rr * 2 + 1] + bv[ni][1]) * gt;
                *reinterpret_cast<float2*>(dst + n) = make_float2(v0, v1);
            }
        }
    }
#undef FILL2
#undef LDF2
#undef MMA2
}

// ---------------- deterministic combine ----------------
__global__ void combine_kernel(float* __restrict__ out) {
    int i = blockIdx.x * blockDim.x + threadIdx.x;
    const int HV = H_ / 4;
    int t = i / HV;
    int h = i - t * HV;
    const float4* p0 = reinterpret_cast<const float4*>(g_ypart) + (size_t)(2 * t) * HV + h;
    const float4* p1 = p0 + HV;
    float4 a = *p0, b = *p1;
    reinterpret_cast<float4*>(out)[i] = make_float4(a.x + b.x, a.y + b.y, a.z + b.z, a.w + b.w);
}

// ---------------- launch ----------------
extern "C" void kernel_launch(void* const* d_in, const int* in_sizes, int n_in,
                              void* d_out, int out_size) {
    const float* x      = (const float*)d_in[0];
    const float* logits = (const float*)d_in[1];
    const float* w13    = (const float*)d_in[2];
    const float* w2     = (const float*)d_in[3];
    const float* b13    = (const float*)d_in[4];
    const float* b2     = (const float*)d_in[5];
    float* out = (float*)d_out;

    static int attr_done = 0;
    if (!attr_done) {
        cudaFuncSetAttribute(gemm1_kernel, cudaFuncAttributeMaxDynamicSharedMemorySize, SMEMSZ);
        cudaFuncSetAttribute(gemm2_kernel, cudaFuncAttributeMaxDynamicSharedMemorySize, SMEMSZ);
        attr_done = 1;
    }

    zero_cnt_kernel<<<1, 32>>>();
    presplit_kernel<<<(T_ * H_ / 4) / 256, 256>>>(x);
    router_kernel<<<T_ / 256, 256>>>(logits);

    convw_kernel<<<(int)(((size_t)E_ * 2 * I_ * H_ + (size_t)E_ * H_ * I_) / 8 / 256), 256>>>(w13, w2);

    dim3 g1(I_ / 64, T_ / 128, E_);    // 32 x 8 x 8
    gemm1_kernel<<<g1, 256, SMEMSZ>>>(b13);

    dim3 g2(H_ / 128, T_ / 128, E_);   // 8 x 8 x 8
    gemm2_kernel<<<g2, 256, SMEMSZ>>>(b2);

    combine_kernel<<<(T_ * H_ / 4) / 256, 256>>>(out);
}

// round 11
// speedup vs baseline: 1.3813x; 1.3813x over previous
#include <cuda_runtime.h>
#include <cuda_bf16.h>
#include <cstdint>

#define E_ 8
#define H_ 1024
#define I_ 2048
#define T_ 1024

// stage layout (bytes): A_hi 64x80 | A_lo 64x80 | B 128x80
#define ATILE 5120
#define BTILE 10240
#define STGB  20480
#define NSTG  3
#define SMEMSZ (NSTG * STGB)          // 61440 B per CTA

// ---------------- scratch ----------------
__device__ int   g_cnt[E_];
__device__ int   g_tok[E_ * T_];
__device__ int   g_slot[E_ * T_];
__device__ float g_gate[E_ * T_];
__device__ __nv_bfloat16 g_xh[T_ * H_];
__device__ __nv_bfloat16 g_xl[T_ * H_];
__device__ __nv_bfloat16 g_w13b[(size_t)E_ * 2 * I_ * H_];
__device__ __nv_bfloat16 g_w2b[(size_t)E_ * H_ * I_];
__device__ __nv_bfloat16 g_acth[(size_t)E_ * T_ * I_];
__device__ __nv_bfloat16 g_actl[(size_t)E_ * T_ * I_];
__device__ float g_ypart[(size_t)T_ * 2 * H_];

// ---------------- helpers ----------------
__device__ __forceinline__ void cp16(uint32_t sa, const void* g) {
    asm volatile("cp.async.cg.shared.global [%0], [%1], 16;\n" :: "r"(sa), "l"(g));
}
__device__ __forceinline__ void cp_commit() { asm volatile("cp.async.commit_group;\n"); }
__device__ __forceinline__ void cp_wait1()  { asm volatile("cp.async.wait_group 1;\n"); }
__device__ __forceinline__ void cp_wait0()  { asm volatile("cp.async.wait_group 0;\n"); }

__device__ __forceinline__ uint32_t pack_bf2(float lo, float hi) {
    uint32_t r;
    asm("cvt.rn.bf16x2.f32 %0, %1, %2;" : "=r"(r) : "f"(hi), "f"(lo));
    return r;
}
__device__ __forceinline__ float bf_rt(float v) {
    return __bfloat162float(__float2bfloat16_rn(v));
}
__device__ __forceinline__ void ldsm4(uint32_t r[4], uint32_t a) {
    asm volatile("ldmatrix.sync.aligned.m8n8.x4.shared.b16 {%0,%1,%2,%3}, [%4];"
        : "=r"(r[0]), "=r"(r[1]), "=r"(r[2]), "=r"(r[3]) : "r"(a));
}
__device__ __forceinline__ void hmma(float c[4], const uint32_t a[4], uint32_t b0, uint32_t b1) {
    asm volatile(
        "mma.sync.aligned.m16n8k16.row.col.f32.bf16.bf16.f32 "
        "{%0,%1,%2,%3}, {%4,%5,%6,%7}, {%8,%9}, {%0,%1,%2,%3};\n"
        : "+f"(c[0]), "+f"(c[1]), "+f"(c[2]), "+f"(c[3])
        : "r"(a[0]), "r"(a[1]), "r"(a[2]), "r"(a[3]), "r"(b0), "r"(b1));
}

// ---------------- small kernels ----------------
__global__ void zero_cnt_kernel() { if (threadIdx.x < E_) g_cnt[threadIdx.x] = 0; }

__global__ void presplit_kernel(const float* __restrict__ x) {
    int i = blockIdx.x * blockDim.x + threadIdx.x;
    float4 v = reinterpret_cast<const float4*>(x)[i];
    float h0 = bf_rt(v.x), h1 = bf_rt(v.y), h2 = bf_rt(v.z), h3 = bf_rt(v.w);
    reinterpret_cast<uint2*>(g_xh)[i] = make_uint2(pack_bf2(v.x, v.y), pack_bf2(v.z, v.w));
    reinterpret_cast<uint2*>(g_xl)[i] =
        make_uint2(pack_bf2(v.x - h0, v.y - h1), pack_bf2(v.z - h2, v.w - h3));
}

__global__ void convw_kernel(const float* __restrict__ w13, const float* __restrict__ w2) {
    size_t i = (size_t)blockIdx.x * blockDim.x + threadIdx.x;
    const size_t N13 = (size_t)E_ * 2 * I_ * H_;
    size_t base = i * 8;
    const float4* src;
    uint2* dst;
    if (base < N13) {
        src = reinterpret_cast<const float4*>(w13 + base);
        dst = reinterpret_cast<uint2*>(g_w13b + base);
    } else {
        base -= N13;
        src = reinterpret_cast<const float4*>(w2 + base);
        dst = reinterpret_cast<uint2*>(g_w2b + base);
    }
    float4 a = __ldg(src), b = __ldg(src + 1);
    dst[0] = make_uint2(pack_bf2(a.x, a.y), pack_bf2(a.z, a.w));
    dst[1] = make_uint2(pack_bf2(b.x, b.y), pack_bf2(b.z, b.w));
}

__global__ void router_kernel(const float* __restrict__ logits) {
    int t = blockIdx.x * blockDim.x + threadIdx.x;
    if (t >= T_) return;
    float l[E_]; float mx = -1e30f;
#pragma unroll
    for (int e = 0; e < E_; e++) { l[e] = logits[t * E_ + e]; mx = fmaxf(mx, l[e]); }
    float p[E_];
#pragma unroll
    for (int e = 0; e < E_; e++) p[e] = __expf(l[e] - mx);
    int i1 = 0, i2 = -1; float v1 = p[0], v2 = -1.0f;
#pragma unroll
    for (int e = 1; e < E_; e++) {
        float pe = p[e];
        if (pe > v1) { v2 = v1; i2 = i1; v1 = pe; i1 = e; }
        else if (pe > v2) { v2 = pe; i2 = e; }
    }
    float inv = 1.0f / (v1 + v2);
    int pos1 = atomicAdd(&g_cnt[i1], 1);
    g_tok[i1 * T_ + pos1] = t; g_slot[i1 * T_ + pos1] = 0; g_gate[i1 * T_ + pos1] = v1 * inv;
    int pos2 = atomicAdd(&g_cnt[i2], 1);
    g_tok[i2 * T_ + pos2] = t; g_slot[i2 * T_ + pos2] = 1; g_gate[i2 * T_ + pos2] = v2 * inv;
}

// =============== GEMM1: 64m x (64G | 64L), 128 thr, 3 CTA/SM, fused GLU ===============
__global__ void __launch_bounds__(128, 3) gemm1_kernel(const float* __restrict__ b13)
{
    int e = blockIdx.z;
    int cnt = g_cnt[e];
    int m0 = blockIdx.y * 64;
    if (m0 >= cnt) return;
    int n0 = blockIdx.x * 64;
    int tid = threadIdx.x;

    extern __shared__ char smem[];
    uint32_t sb = (uint32_t)__cvta_generic_to_shared(smem);

    // ---- fill setup: lr = row (0..63), lh = 32B half of 64B chunk-row ----
    int lr = tid >> 1, lh = tid & 1;
    int mg = m0 + lr; if (mg >= cnt) mg = cnt - 1;
    size_t axoff = (size_t)g_tok[e * T_ + mg] * H_ + lh * 16;
    const __nv_bfloat16* ah = g_xh + axoff;
    const __nv_bfloat16* al = g_xl + axoff;
    const __nv_bfloat16* bg = g_w13b + ((size_t)e * 2 * I_ + n0 + lr) * H_ + lh * 16;
    const __nv_bfloat16* bl = g_w13b + ((size_t)e * 2 * I_ + I_ + n0 + lr) * H_ + lh * 16;
    uint32_t adst = sb + lr * 80 + lh * 32;
    uint32_t bdst = sb + 2 * ATILE + lr * 80 + lh * 32;

#define FILL1(c, s) {                                                    \
        uint32_t o_ = (s) * STGB;                                        \
        cp16(adst + o_, ah + (c) * 32); cp16(adst + o_ + 16, ah + (c) * 32 + 8); \
        cp16(adst + o_ + ATILE, al + (c) * 32); cp16(adst + o_ + ATILE + 16, al + (c) * 32 + 8); \
        cp16(bdst + o_, bg + (c) * 32); cp16(bdst + o_ + 16, bg + (c) * 32 + 8); \
        cp16(bdst + o_ + ATILE, bl + (c) * 32); cp16(bdst + o_ + ATILE + 16, bl + (c) * 32 + 8); \
        cp_commit(); }

    // ---- compute setup: 4 warps = 2m x 2n, warp tile 32m x (32G + 32L) ----
    int lane = tid & 31, warp = tid >> 5;
    int wm = warp & 1, wn = warp >> 1;
    int gid = lane >> 2, tig = lane & 3;

    uint32_t aAH = sb + (wm * 32 + (lane & 15)) * 80 + (lane >> 4) * 16;
    uint32_t aAL = aAH + ATILE;
    int brl = ((lane >> 4) & 1) * 8 + (lane & 7);
    int bko = ((lane >> 3) & 1) * 16;
    uint32_t bB = sb + 2 * ATILE + bko;
    uint32_t tG0 = bB + (wn * 32 + brl) * 80;
    uint32_t tG1 = tG0 + 16 * 80;
    uint32_t tL0 = tG0 + ATILE;
    uint32_t tL1 = tG1 + ATILE;

    uint32_t bG[2][2][4], bL[2][2][4], afh[2][2][4], afl[2][2][4];
    float accG[2][4][4], accL[2][4][4];
#pragma unroll
    for (int i = 0; i < 2; i++)
#pragma unroll
        for (int j = 0; j < 4; j++)
#pragma unroll
            for (int k = 0; k < 4; k++) { accG[i][j][k] = 0.f; accL[i][j][k] = 0.f; }

#define LDF1(p, ko) {                                                    \
        ldsm4(bG[p][0], tG0 + (ko)); ldsm4(bG[p][1], tG1 + (ko));        \
        ldsm4(bL[p][0], tL0 + (ko)); ldsm4(bL[p][1], tL1 + (ko));        \
        ldsm4(afh[p][0], aAH + (ko)); ldsm4(afh[p][1], aAH + (ko) + 16 * 80); \
        ldsm4(afl[p][0], aAL + (ko)); ldsm4(afl[p][1], aAL + (ko) + 16 * 80); }

#define MMA1(p) {                                                        \
        _Pragma("unroll")                                                \
        for (int mi = 0; mi < 2; mi++) {                                 \
            hmma(accG[mi][0], afh[p][mi], bG[p][0][0], bG[p][0][1]);     \
            hmma(accG[mi][1], afh[p][mi], bG[p][0][2], bG[p][0][3]);     \
            hmma(accG[mi][2], afh[p][mi], bG[p][1][0], bG[p][1][1]);     \
            hmma(accG[mi][3], afh[p][mi], bG[p][1][2], bG[p][1][3]);     \
            hmma(accL[mi][0], afh[p][mi], bL[p][0][0], bL[p][0][1]);     \
            hmma(accL[mi][1], afh[p][mi], bL[p][0][2], bL[p][0][3]);     \
            hmma(accL[mi][2], afh[p][mi], bL[p][1][0], bL[p][1][1]);     \
            hmma(accL[mi][3], afh[p][mi], bL[p][1][2], bL[p][1][3]);     \
        }                                                                \
        _Pragma("unroll")                                                \
        for (int mi = 0; mi < 2; mi++) {                                 \
            hmma(accG[mi][0], afl[p][mi], bG[p][0][0], bG[p][0][1]);     \
            hmma(accG[mi][1], afl[p][mi], bG[p][0][2], bG[p][0][3]);     \
            hmma(accG[mi][2], afl[p][mi], bG[p][1][0], bG[p][1][1]);     \
            hmma(accG[mi][3], afl[p][mi], bG[p][1][2], bG[p][1][3]);     \
            hmma(accL[mi][0], afl[p][mi], bL[p][0][0], bL[p][0][1]);     \
            hmma(accL[mi][1], afl[p][mi], bL[p][0][2], bL[p][0][3]);     \
            hmma(accL[mi][2], afl[p][mi], bL[p][1][0], bL[p][1][1]);     \
            hmma(accL[mi][3], afl[p][mi], bL[p][1][2], bL[p][1][3]);     \
        } }

    FILL1(0, 0); FILL1(1, 1);

    const int NK = H_ / 32;   // 32
#pragma unroll 1
    for (int kt = 0; kt < NK; ++kt) {
        int st = kt % NSTG;
        if (kt + 1 < NK) cp_wait1(); else cp_wait0();
        __syncthreads();
        int cf = kt + 2;
        if (cf < NK) { FILL1(cf, cf % NSTG); } else { cp_commit(); }
        uint32_t so = st * STGB;
        LDF1(0, so);
        LDF1(1, so + 32);
        MMA1(0);
        MMA1(1);
    }

    // ---- epilogue: bias + GLU + bf16 hi/lo split store ----
    float bgv[4][2], blv[4][2];
#pragma unroll
    for (int ni = 0; ni < 4; ni++) {
        int n = n0 + wn * 32 + ni * 8 + tig * 2;
        bgv[ni][0] = __ldg(&b13[(size_t)e * 2 * I_ + n]);
        bgv[ni][1] = __ldg(&b13[(size_t)e * 2 * I_ + n + 1]);
        blv[ni][0] = __ldg(&b13[(size_t)e * 2 * I_ + I_ + n]);
        blv[ni][1] = __ldg(&b13[(size_t)e * 2 * I_ + I_ + n + 1]);
    }
    size_t actbase = (size_t)e * T_ * I_;
#pragma unroll
    for (int mi = 0; mi < 2; mi++) {
#pragma unroll
        for (int rr = 0; rr < 2; rr++) {
            int m = m0 + wm * 32 + mi * 16 + gid + rr * 8;
            if (m >= cnt) continue;
            size_t rowoff = actbase + (size_t)m * I_;
#pragma unroll
            for (int ni = 0; ni < 4; ni++) {
                int n = n0 + wn * 32 + ni * 8 + tig * 2;
                float g0 = accG[mi][ni][rr * 2 + 0] + bgv[ni][0];
                float g1 = accG[mi][ni][rr * 2 + 1] + bgv[ni][1];
                float l0 = accL[mi][ni][rr * 2 + 0] + blv[ni][0];
                float l1 = accL[mi][ni][rr * 2 + 1] + blv[ni][1];
                float a0 = g0 * (1.f / (1.f + __expf(-1.702f * g0))) * (l0 + 1.0f);
                float a1 = g1 * (1.f / (1.f + __expf(-1.702f * g1))) * (l1 + 1.0f);
                float h0 = bf_rt(a0), h1 = bf_rt(a1);
                *reinterpret_cast<uint32_t*>(g_acth + rowoff + n) = pack_bf2(a0, a1);
                *reinterpret_cast<uint32_t*>(g_actl + rowoff + n) = pack_bf2(a0 - h0, a1 - h1);
            }
        }
    }
#undef FILL1
#undef LDF1
#undef MMA1
}

// =============== GEMM2: 64m x 128n, 128 thr, 3 CTA/SM, fused bias+gate+scatter ===============
__global__ void __launch_bounds__(128, 3) gemm2_kernel(const float* __restrict__ b2)
{
    int e = blockIdx.z;
    int cnt = g_cnt[e];
    int m0 = blockIdx.y * 64;
    if (m0 >= cnt) return;
    int n0 = blockIdx.x * 128;
    int tid = threadIdx.x;

    extern __shared__ char smem[];
    uint32_t sb = (uint32_t)__cvta_generic_to_shared(smem);

    int lr = tid >> 1, lh = tid & 1;
    int mg = m0 + lr; if (mg >= cnt) mg = cnt - 1;
    size_t aoff = (size_t)(e * T_ + mg) * I_ + lh * 16;
    const __nv_bfloat16* ah = g_acth + aoff;
    const __nv_bfloat16* al = g_actl + aoff;
    const __nv_bfloat16* b1p = g_w2b + (size_t)(e * H_ + n0 + lr) * I_ + lh * 16;
    const __nv_bfloat16* b2p = g_w2b + (size_t)(e * H_ + n0 + 64 + lr) * I_ + lh * 16;
    uint32_t adst = sb + lr * 80 + lh * 32;
    uint32_t bdst = sb + 2 * ATILE + lr * 80 + lh * 32;

#define FILL2(c, s) {                                                    \
        uint32_t o_ = (s) * STGB;                                        \
        cp16(adst + o_, ah + (c) * 32); cp16(adst + o_ + 16, ah + (c) * 32 + 8); \
        cp16(adst + o_ + ATILE, al + (c) * 32); cp16(adst + o_ + ATILE + 16, al + (c) * 32 + 8); \
        cp16(bdst + o_, b1p + (c) * 32); cp16(bdst + o_ + 16, b1p + (c) * 32 + 8); \
        cp16(bdst + o_ + ATILE, b2p + (c) * 32); cp16(bdst + o_ + ATILE + 16, b2p + (c) * 32 + 8); \
        cp_commit(); }

    // ---- compute setup: 4 warps = 2m x 2n, warp tile 32m x 64n ----
    int lane = tid & 31, warp = tid >> 5;
    int wm = warp & 1, wn = warp >> 1;
    int gid = lane >> 2, tig = lane & 3;

    uint32_t aAH = sb + (wm * 32 + (lane & 15)) * 80 + (lane >> 4) * 16;
    uint32_t aAL = aAH + ATILE;
    int brl = ((lane >> 4) & 1) * 8 + (lane & 7);
    int bko = ((lane >> 3) & 1) * 16;
    uint32_t bB = sb + 2 * ATILE + bko;
    uint32_t tb[4];
#pragma unroll
    for (int g = 0; g < 4; g++) tb[g] = bB + (wn * 64 + g * 16 + brl) * 80;

    uint32_t bfr[2][4][4], afh[2][2][4], afl[2][2][4];
    float acc[2][8][4];
#pragma unroll
    for (int i = 0; i < 2; i++)
#pragma unroll
        for (int j = 0; j < 8; j++)
#pragma unroll
            for (int k = 0; k < 4; k++) acc[i][j][k] = 0.f;

#define LDF2(p, ko) {                                                    \
        _Pragma("unroll")                                                \
        for (int g = 0; g < 4; g++) ldsm4(bfr[p][g], tb[g] + (ko));      \
        ldsm4(afh[p][0], aAH + (ko)); ldsm4(afh[p][1], aAH + (ko) + 16 * 80); \
        ldsm4(afl[p][0], aAL + (ko)); ldsm4(afl[p][1], aAL + (ko) + 16 * 80); }

#define MMA2(p) {                                                        \
        _Pragma("unroll")                                                \
        for (int g = 0; g < 4; g++)                                      \
            _Pragma("unroll")                                            \
            for (int mi = 0; mi < 2; mi++) {                             \
                hmma(acc[mi][2 * g],     afh[p][mi], bfr[p][g][0], bfr[p][g][1]); \
                hmma(acc[mi][2 * g + 1], afh[p][mi], bfr[p][g][2], bfr[p][g][3]); \
            }                                                            \
        _Pragma("unroll")                                                \
        for (int g = 0; g < 4; g++)                                      \
            _Pragma("unroll")                                            \
            for (int mi = 0; mi < 2; mi++) {                             \
                hmma(acc[mi][2 * g],     afl[p][mi], bfr[p][g][0], bfr[p][g][1]); \
                hmma(acc[mi][2 * g + 1], afl[p][mi], bfr[p][g][2], bfr[p][g][3]); \
            } }

    FILL2(0, 0); FILL2(1, 1);

    const int NK = I_ / 32;   // 64
#pragma unroll 1
    for (int kt = 0; kt < NK; ++kt) {
        int st = kt % NSTG;
        if (kt + 1 < NK) cp_wait1(); else cp_wait0();
        __syncthreads();
        int cf = kt + 2;
        if (cf < NK) { FILL2(cf, cf % NSTG); } else { cp_commit(); }
        uint32_t so = st * STGB;
        LDF2(0, so);
        LDF2(1, so + 32);
        MMA2(0);
        MMA2(1);
    }

    float bv[8][2];
#pragma unroll
    for (int ni = 0; ni < 8; ni++) {
        int n = n0 + wn * 64 + ni * 8 + tig * 2;
        bv[ni][0] = __ldg(&b2[(size_t)e * H_ + n]);
        bv[ni][1] = __ldg(&b2[(size_t)e * H_ + n + 1]);
    }
#pragma unroll
    for (int mi = 0; mi < 2; mi++) {
#pragma unroll
        for (int rr = 0; rr < 2; rr++) {
            int m = m0 + wm * 32 + mi * 16 + gid + rr * 8;
            if (m >= cnt) continue;
            int tok = g_tok[e * T_ + m];
            int slot = g_slot[e * T_ + m];
            float gt = g_gate[e * T_ + m];
            float* dst = g_ypart + (size_t)(tok * 2 + slot) * H_;
#pragma unroll
            for (int ni = 0; ni < 8; ni++) {
                int n = n0 + wn * 64 + ni * 8 + tig * 2;
                float v0 = (acc[mi][ni][rr * 2 + 0] + bv[ni][0]) * gt;
                float v1 = (acc[mi][ni][rr * 2 + 1] + bv[ni][1]) * gt;
                *reinterpret_cast<float2*>(dst + n) = make_float2(v0, v1);
            }
        }
    }
#undef FILL2
#undef LDF2
#undef MMA2
}

// ---------------- deterministic combine ----------------
__global__ void combine_kernel(float* __restrict__ out) {
    int i = blockIdx.x * blockDim.x + threadIdx.x;
    const int HV = H_ / 4;
    int t = i / HV;
    int h = i - t * HV;
    const float4* p0 = reinterpret_cast<const float4*>(g_ypart) + (size_t)(2 * t) * HV + h;
    const float4* p1 = p0 + HV;
    float4 a = *p0, b = *p1;
    reinterpret_cast<float4*>(out)[i] = make_float4(a.x + b.x, a.y + b.y, a.z + b.z, a.w + b.w);
}

// ---------------- launch ----------------
extern "C" void kernel_launch(void* const* d_in, const int* in_sizes, int n_in,
                              void* d_out, int out_size) {
    const float* x      = (const float*)d_in[0];
    const float* logits = (const float*)d_in[1];
    const float* w13    = (const float*)d_in[2];
    const float* w2     = (const float*)d_in[3];
    const float* b13    = (const float*)d_in[4];
    const float* b2     = (const float*)d_in[5];
    float* out = (float*)d_out;

    static int attr_done = 0;
    if (!attr_done) {
        cudaFuncSetAttribute(gemm1_kernel, cudaFuncAttributeMaxDynamicSharedMemorySize, SMEMSZ);
        cudaFuncSetAttribute(gemm2_kernel, cudaFuncAttributeMaxDynamicSharedMemorySize, SMEMSZ);
        attr_done = 1;
    }

    zero_cnt_kernel<<<1, 32>>>();
    presplit_kernel<<<(T_ * H_ / 4) / 256, 256>>>(x);
    router_kernel<<<T_ / 256, 256>>>(logits);

    convw_kernel<<<(int)(((size_t)E_ * 2 * I_ * H_ + (size_t)E_ * H_ * I_) / 8 / 256), 256>>>(w13, w2);

    dim3 g1(I_ / 64, T_ / 64, E_);     // 32 x 16 x 8
    gemm1_kernel<<<g1, 128, SMEMSZ>>>(b13);

    dim3 g2(H_ / 128, T_ / 64, E_);    // 8 x 16 x 8
    gemm2_kernel<<<g2, 128, SMEMSZ>>>(b2);

    combine_kernel<<<(T_ * H_ / 4) / 256, 256>>>(out);
}

// round 12
// speedup vs baseline: 1.8054x; 1.3070x over previous
#include <cuda_runtime.h>
#include <cuda_fp16.h>
#include <cstdint>

#define E_ 8
#define H_ 1024
#define I_ 2048
#define T_ 1024

// stage layout (bytes): A 64x80 | B 128x80
#define ATILE 5120
#define STGB  15360
#define NSTG  4
#define SMEMSZ (NSTG * STGB)          // 61440 B per CTA

// ---------------- scratch ----------------
__device__ int   g_cnt[E_];
__device__ int   g_tok[E_ * T_];
__device__ int   g_slot[E_ * T_];
__device__ float g_gate[E_ * T_];
__device__ __half g_xh[T_ * H_];
__device__ __half g_w13h[(size_t)E_ * 2 * I_ * H_];
__device__ __half g_w2h[(size_t)E_ * H_ * I_];
__device__ __half g_acth[(size_t)E_ * T_ * I_];
__device__ float g_ypart[(size_t)T_ * 2 * H_];

// ---------------- helpers ----------------
__device__ __forceinline__ void cp16(uint32_t sa, const void* g) {
    asm volatile("cp.async.cg.shared.global [%0], [%1], 16;\n" :: "r"(sa), "l"(g));
}
__device__ __forceinline__ void cp_commit() { asm volatile("cp.async.commit_group;\n"); }
__device__ __forceinline__ void cp_wait2()  { asm volatile("cp.async.wait_group 2;\n"); }
__device__ __forceinline__ void cp_wait0()  { asm volatile("cp.async.wait_group 0;\n"); }

// pack two f32 -> f16x2; 'lo' lands in the lower 16 bits
__device__ __forceinline__ uint32_t pack_h2(float lo, float hi) {
    uint32_t r;
    asm("cvt.rn.f16x2.f32 %0, %1, %2;" : "=r"(r) : "f"(hi), "f"(lo));
    return r;
}
__device__ __forceinline__ void ldsm4(uint32_t r[4], uint32_t a) {
    asm volatile("ldmatrix.sync.aligned.m8n8.x4.shared.b16 {%0,%1,%2,%3}, [%4];"
        : "=r"(r[0]), "=r"(r[1]), "=r"(r[2]), "=r"(r[3]) : "r"(a));
}
__device__ __forceinline__ void hmma(float c[4], const uint32_t a[4], uint32_t b0, uint32_t b1) {
    asm volatile(
        "mma.sync.aligned.m16n8k16.row.col.f32.f16.f16.f32 "
        "{%0,%1,%2,%3}, {%4,%5,%6,%7}, {%8,%9}, {%0,%1,%2,%3};\n"
        : "+f"(c[0]), "+f"(c[1]), "+f"(c[2]), "+f"(c[3])
        : "r"(a[0]), "r"(a[1]), "r"(a[2]), "r"(a[3]), "r"(b0), "r"(b1));
}

// ---------------- small kernels ----------------
__global__ void zero_cnt_kernel() { if (threadIdx.x < E_) g_cnt[threadIdx.x] = 0; }

__global__ void presplit_kernel(const float* __restrict__ x) {
    int i = blockIdx.x * blockDim.x + threadIdx.x;    // over T_*H_/4
    float4 v = reinterpret_cast<const float4*>(x)[i];
    reinterpret_cast<uint2*>(g_xh)[i] = make_uint2(pack_h2(v.x, v.y), pack_h2(v.z, v.w));
}

// convert w13 + w2 (f32 -> fp16, exact for MXFP4-qdq values)
__global__ void convw_kernel(const float* __restrict__ w13, const float* __restrict__ w2) {
    size_t i = (size_t)blockIdx.x * blockDim.x + threadIdx.x;
    const size_t N13 = (size_t)E_ * 2 * I_ * H_;
    size_t base = i * 8;
    const float4* src;
    uint2* dst;
    if (base < N13) {
        src = reinterpret_cast<const float4*>(w13 + base);
        dst = reinterpret_cast<uint2*>(g_w13h + base);
    } else {
        base -= N13;
        src = reinterpret_cast<const float4*>(w2 + base);
        dst = reinterpret_cast<uint2*>(g_w2h + base);
    }
    float4 a = __ldg(src), b = __ldg(src + 1);
    dst[0] = make_uint2(pack_h2(a.x, a.y), pack_h2(a.z, a.w));
    dst[1] = make_uint2(pack_h2(b.x, b.y), pack_h2(b.z, b.w));
}

__global__ void router_kernel(const float* __restrict__ logits) {
    int t = blockIdx.x * blockDim.x + threadIdx.x;
    if (t >= T_) return;
    float l[E_]; float mx = -1e30f;
#pragma unroll
    for (int e = 0; e < E_; e++) { l[e] = logits[t * E_ + e]; mx = fmaxf(mx, l[e]); }
    float p[E_];
#pragma unroll
    for (int e = 0; e < E_; e++) p[e] = __expf(l[e] - mx);
    int i1 = 0, i2 = -1; float v1 = p[0], v2 = -1.0f;
#pragma unroll
    for (int e = 1; e < E_; e++) {
        float pe = p[e];
        if (pe > v1) { v2 = v1; i2 = i1; v1 = pe; i1 = e; }
        else if (pe > v2) { v2 = pe; i2 = e; }
    }
    float inv = 1.0f / (v1 + v2);
    int pos1 = atomicAdd(&g_cnt[i1], 1);
    g_tok[i1 * T_ + pos1] = t; g_slot[i1 * T_ + pos1] = 0; g_gate[i1 * T_ + pos1] = v1 * inv;
    int pos2 = atomicAdd(&g_cnt[i2], 1);
    g_tok[i2 * T_ + pos2] = t; g_slot[i2 * T_ + pos2] = 1; g_gate[i2 * T_ + pos2] = v2 * inv;
}

// =============== GEMM1: 64m x (64G | 64L), fp16 single-pass, fused GLU ===============
__global__ void __launch_bounds__(128, 3) gemm1_kernel(const float* __restrict__ b13)
{
    int e = blockIdx.z;
    int cnt = g_cnt[e];
    int m0 = blockIdx.y * 64;
    if (m0 >= cnt) return;
    int n0 = blockIdx.x * 64;
    int tid = threadIdx.x;

    extern __shared__ char smem[];
    uint32_t sb = (uint32_t)__cvta_generic_to_shared(smem);

    // ---- fill setup: lr = row (0..63), lh = 32B half of the 64B chunk-row ----
    int lr = tid >> 1, lh = tid & 1;
    int mg = m0 + lr; if (mg >= cnt) mg = cnt - 1;
    const __half* ax = g_xh + (size_t)g_tok[e * T_ + mg] * H_ + lh * 16;
    const __half* bg = g_w13h + ((size_t)e * 2 * I_ + n0 + lr) * H_ + lh * 16;
    const __half* bl = g_w13h + ((size_t)e * 2 * I_ + I_ + n0 + lr) * H_ + lh * 16;
    uint32_t adst = sb + lr * 80 + lh * 32;
    uint32_t bdst = sb + ATILE + lr * 80 + lh * 32;     // G rows; L rows at +5120

#define FILL1(c, s) {                                                    \
        uint32_t o_ = (s) * STGB;                                        \
        cp16(adst + o_, ax + (c) * 32); cp16(adst + o_ + 16, ax + (c) * 32 + 8); \
        cp16(bdst + o_, bg + (c) * 32); cp16(bdst + o_ + 16, bg + (c) * 32 + 8); \
        cp16(bdst + o_ + 5120, bl + (c) * 32); cp16(bdst + o_ + 5120 + 16, bl + (c) * 32 + 8); \
        cp_commit(); }

    // ---- compute setup: 4 warps = 2m x 2n; warp tile 32m x (32G + 32L) ----
    int lane = tid & 31, warp = tid >> 5;
    int wm = warp & 1, wn = warp >> 1;
    int gid = lane >> 2, tig = lane & 3;

    uint32_t aA = sb + (wm * 32 + (lane & 15)) * 80 + (lane >> 4) * 16;
    int brl = ((lane >> 4) & 1) * 8 + (lane & 7);
    int bko = ((lane >> 3) & 1) * 16;
    uint32_t bB = sb + ATILE + bko;
    uint32_t tG0 = bB + (wn * 32 + brl) * 80;
    uint32_t tG1 = tG0 + 16 * 80;
    uint32_t tL0 = tG0 + 64 * 80;
    uint32_t tL1 = tG1 + 64 * 80;

    uint32_t bG[2][2][4], bL[2][2][4], af[2][2][4];
    float accG[2][4][4], accL[2][4][4];
#pragma unroll
    for (int i = 0; i < 2; i++)
#pragma unroll
        for (int j = 0; j < 4; j++)
#pragma unroll
            for (int k = 0; k < 4; k++) { accG[i][j][k] = 0.f; accL[i][j][k] = 0.f; }

#define LDF1(p, ko) {                                                    \
        ldsm4(bG[p][0], tG0 + (ko)); ldsm4(bG[p][1], tG1 + (ko));        \
        ldsm4(bL[p][0], tL0 + (ko)); ldsm4(bL[p][1], tL1 + (ko));        \
        ldsm4(af[p][0], aA + (ko)); ldsm4(af[p][1], aA + (ko) + 16 * 80); }

#define MMA1(p) {                                                        \
        _Pragma("unroll")                                                \
        for (int mi = 0; mi < 2; mi++) {                                 \
            hmma(accG[mi][0], af[p][mi], bG[p][0][0], bG[p][0][1]);      \
            hmma(accG[mi][1], af[p][mi], bG[p][0][2], bG[p][0][3]);      \
            hmma(accG[mi][2], af[p][mi], bG[p][1][0], bG[p][1][1]);      \
            hmma(accG[mi][3], af[p][mi], bG[p][1][2], bG[p][1][3]);      \
            hmma(accL[mi][0], af[p][mi], bL[p][0][0], bL[p][0][1]);      \
            hmma(accL[mi][1], af[p][mi], bL[p][0][2], bL[p][0][3]);      \
            hmma(accL[mi][2], af[p][mi], bL[p][1][0], bL[p][1][1]);      \
            hmma(accL[mi][3], af[p][mi], bL[p][1][2], bL[p][1][3]);      \
        } }

    FILL1(0, 0); FILL1(1, 1); FILL1(2, 2);

    const int NK = H_ / 32;   // 32
#pragma unroll 1
    for (int kt = 0; kt < NK; ++kt) {
        int st = kt % NSTG;
        cp_wait2();
        __syncthreads();
        int cf = kt + 3;
        if (cf < NK) { FILL1(cf, cf % NSTG); } else { cp_commit(); }
        uint32_t so = st * STGB;
        LDF1(0, so);
        LDF1(1, so + 32);
        MMA1(0);
        MMA1(1);
    }

    // ---- epilogue: bias + GLU + fp16 store ----
    float bgv[4][2], blv[4][2];
#pragma unroll
    for (int ni = 0; ni < 4; ni++) {
        int n = n0 + wn * 32 + ni * 8 + tig * 2;
        bgv[ni][0] = __ldg(&b13[(size_t)e * 2 * I_ + n]);
        bgv[ni][1] = __ldg(&b13[(size_t)e * 2 * I_ + n + 1]);
        blv[ni][0] = __ldg(&b13[(size_t)e * 2 * I_ + I_ + n]);
        blv[ni][1] = __ldg(&b13[(size_t)e * 2 * I_ + I_ + n + 1]);
    }
    size_t actbase = (size_t)e * T_ * I_;
#pragma unroll
    for (int mi = 0; mi < 2; mi++) {
#pragma unroll
        for (int rr = 0; rr < 2; rr++) {
            int m = m0 + wm * 32 + mi * 16 + gid + rr * 8;
            if (m >= cnt) continue;
            size_t rowoff = actbase + (size_t)m * I_;
#pragma unroll
            for (int ni = 0; ni < 4; ni++) {
                int n = n0 + wn * 32 + ni * 8 + tig * 2;
                float g0 = accG[mi][ni][rr * 2 + 0] + bgv[ni][0];
                float g1 = accG[mi][ni][rr * 2 + 1] + bgv[ni][1];
                float l0 = accL[mi][ni][rr * 2 + 0] + blv[ni][0];
                float l1 = accL[mi][ni][rr * 2 + 1] + blv[ni][1];
                float a0 = g0 * (1.f / (1.f + __expf(-1.702f * g0))) * (l0 + 1.0f);
                float a1 = g1 * (1.f / (1.f + __expf(-1.702f * g1))) * (l1 + 1.0f);
                *reinterpret_cast<uint32_t*>(g_acth + rowoff + n) = pack_h2(a0, a1);
            }
        }
    }
#undef FILL1
#undef LDF1
#undef MMA1
}

// =============== GEMM2: 64m x 128n, fp16 single-pass, fused bias+gate+scatter ===============
__global__ void __launch_bounds__(128, 3) gemm2_kernel(const float* __restrict__ b2)
{
    int e = blockIdx.z;
    int cnt = g_cnt[e];
    int m0 = blockIdx.y * 64;
    if (m0 >= cnt) return;
    int n0 = blockIdx.x * 128;
    int tid = threadIdx.x;

    extern __shared__ char smem[];
    uint32_t sb = (uint32_t)__cvta_generic_to_shared(smem);

    int lr = tid >> 1, lh = tid & 1;
    int mg = m0 + lr; if (mg >= cnt) mg = cnt - 1;
    const __half* ax = g_acth + (size_t)(e * T_ + mg) * I_ + lh * 16;
    const __half* b1p = g_w2h + (size_t)(e * H_ + n0 + lr) * I_ + lh * 16;
    const __half* b2p = g_w2h + (size_t)(e * H_ + n0 + 64 + lr) * I_ + lh * 16;
    uint32_t adst = sb + lr * 80 + lh * 32;
    uint32_t bdst = sb + ATILE + lr * 80 + lh * 32;

#define FILL2(c, s) {                                                    \
        uint32_t o_ = (s) * STGB;                                        \
        cp16(adst + o_, ax + (c) * 32); cp16(adst + o_ + 16, ax + (c) * 32 + 8); \
        cp16(bdst + o_, b1p + (c) * 32); cp16(bdst + o_ + 16, b1p + (c) * 32 + 8); \
        cp16(bdst + o_ + 5120, b2p + (c) * 32); cp16(bdst + o_ + 5120 + 16, b2p + (c) * 32 + 8); \
        cp_commit(); }

    // ---- compute setup: 4 warps = 2m x 2n; warp tile 32m x 64n ----
    int lane = tid & 31, warp = tid >> 5;
    int wm = warp & 1, wn = warp >> 1;
    int gid = lane >> 2, tig = lane & 3;

    uint32_t aA = sb + (wm * 32 + (lane & 15)) * 80 + (lane >> 4) * 16;
    int brl = ((lane >> 4) & 1) * 8 + (lane & 7);
    int bko = ((lane >> 3) & 1) * 16;
    uint32_t bB = sb + ATILE + bko;
    uint32_t tb[4];
#pragma unroll
    for (int g = 0; g < 4; g++) tb[g] = bB + (wn * 64 + g * 16 + brl) * 80;

    uint32_t bfr[2][4][4], af[2][2][4];
    float acc[2][8][4];
#pragma unroll
    for (int i = 0; i < 2; i++)
#pragma unroll
        for (int j = 0; j < 8; j++)
#pragma unroll
            for (int k = 0; k < 4; k++) acc[i][j][k] = 0.f;

#define LDF2(p, ko) {                                                    \
        _Pragma("unroll")                                                \
        for (int g = 0; g < 4; g++) ldsm4(bfr[p][g], tb[g] + (ko));      \
        ldsm4(af[p][0], aA + (ko)); ldsm4(af[p][1], aA + (ko) + 16 * 80); }

#define MMA2(p) {                                                        \
        _Pragma("unroll")                                                \
        for (int g = 0; g < 4; g++)                                      \
            _Pragma("unroll")                                            \
            for (int mi = 0; mi < 2; mi++) {                             \
                hmma(acc[mi][2 * g],     af[p][mi], bfr[p][g][0], bfr[p][g][1]); \
                hmma(acc[mi][2 * g + 1], af[p][mi], bfr[p][g][2], bfr[p][g][3]); \
            } }

    FILL2(0, 0); FILL2(1, 1); FILL2(2, 2);

    const int NK = I_ / 32;   // 64
#pragma unroll 1
    for (int kt = 0; kt < NK; ++kt) {
        int st = kt % NSTG;
        cp_wait2();
        __syncthreads();
        int cf = kt + 3;
        if (cf < NK) { FILL2(cf, cf % NSTG); } else { cp_commit(); }
        uint32_t so = st * STGB;
        LDF2(0, so);
        LDF2(1, so + 32);
        MMA2(0);
        MMA2(1);
    }

    float bv[8][2];
#pragma unroll
    for (int ni = 0; ni < 8; ni++) {
        int n = n0 + wn * 64 + ni * 8 + tig * 2;
        bv[ni][0] = __ldg(&b2[(size_t)e * H_ + n]);
        bv[ni][1] = __ldg(&b2[(size_t)e * H_ + n + 1]);
    }
#pragma unroll
    for (int mi = 0; mi < 2; mi++) {
#pragma unroll
        for (int rr = 0; rr < 2; rr++) {
            int m = m0 + wm * 32 + mi * 16 + gid + rr * 8;
            if (m >= cnt) continue;
            int tok = g_tok[e * T_ + m];
            int slot = g_slot[e * T_ + m];
            float gt = g_gate[e * T_ + m];
            float* dst = g_ypart + (size_t)(tok * 2 + slot) * H_;
#pragma unroll
            for (int ni = 0; ni < 8; ni++) {
                int n = n0 + wn * 64 + ni * 8 + tig * 2;
                float v0 = (acc[mi][ni][rr * 2 + 0] + bv[ni][0]) * gt;
                float v1 = (acc[mi][ni][rr * 2 + 1] + bv[ni][1]) * gt;
                *reinterpret_cast<float2*>(dst + n) = make_float2(v0, v1);
            }
        }
    }
#undef FILL2
#undef LDF2
#undef MMA2
}

// ---------------- deterministic combine ----------------
__global__ void combine_kernel(float* __restrict__ out) {
    int i = blockIdx.x * blockDim.x + threadIdx.x;
    const int HV = H_ / 4;
    int t = i / HV;
    int h = i - t * HV;
    const float4* p0 = reinterpret_cast<const float4*>(g_ypart) + (size_t)(2 * t) * HV + h;
    const float4* p1 = p0 + HV;
    float4 a = *p0, b = *p1;
    reinterpret_cast<float4*>(out)[i] = make_float4(a.x + b.x, a.y + b.y, a.z + b.z, a.w + b.w);
}

// ---------------- launch ----------------
extern "C" void kernel_launch(void* const* d_in, const int* in_sizes, int n_in,
                              void* d_out, int out_size) {
    const float* x      = (const float*)d_in[0];
    const float* logits = (const float*)d_in[1];
    const float* w13    = (const float*)d_in[2];
    const float* w2     = (const float*)d_in[3];
    const float* b13    = (const float*)d_in[4];
    const float* b2     = (const float*)d_in[5];
    float* out = (float*)d_out;

    static int attr_done = 0;
    if (!attr_done) {
        cudaFuncSetAttribute(gemm1_kernel, cudaFuncAttributeMaxDynamicSharedMemorySize, SMEMSZ);
        cudaFuncSetAttribute(gemm2_kernel, cudaFuncAttributeMaxDynamicSharedMemorySize, SMEMSZ);
        attr_done = 1;
    }

    zero_cnt_kernel<<<1, 32>>>();
    presplit_kernel<<<(T_ * H_ / 4) / 256, 256>>>(x);
    router_kernel<<<T_ / 256, 256>>>(logits);

    convw_kernel<<<(int)(((size_t)E_ * 2 * I_ * H_ + (size_t)E_ * H_ * I_) / 8 / 256), 256>>>(w13, w2);

    dim3 g1(I_ / 64, T_ / 64, E_);     // 32 x 16 x 8
    gemm1_kernel<<<g1, 128, SMEMSZ>>>(b13);

    dim3 g2(H_ / 128, T_ / 64, E_);    // 8 x 16 x 8
    gemm2_kernel<<<g2, 128, SMEMSZ>>>(b2);

    combine_kernel<<<(T_ * H_ / 4) / 256, 256>>>(out);
}